// round 1
// baseline (speedup 1.0000x reference)
#include <cuda_runtime.h>
#include <math.h>

#define BATCH 32
#define CCH   3
#define HH    224
#define NTOK  196
#define PD    768
#define DIM   512
#define NCLS  1000
#define NP    224          // padded token count (multiple of 16/32)
#define NPS   (NP*NP)      // 50176
#define SLK_M (64*NP)      // tail slack: tile row overruns up to row 255
#define SLK_QV (64*DIM)
#define ITERS 50
#define LNEPS 1e-5f

// ---------------- scratch (static device memory; no allocation) ----------------
__device__ float g_x[BATCH*NTOK*PD];
__device__ float g_Q[BATCH*NP*DIM + SLK_QV];
__device__ float g_V[BATCH*NP*DIM + SLK_QV];
__device__ float g_A[BATCH*NPS + SLK_M];
__device__ float g_Minv[BATCH*NPS + SLK_M];
__device__ float g_P[BATCH*NPS + SLK_M];
__device__ float g_Zbuf[2][BATCH*NPS + SLK_M];
__device__ float g_Ubuf[2][BATCH*NPS + SLK_M];
__device__ float g_pooled[BATCH*DIM];

// ---------------- helpers ----------------
__device__ __forceinline__ void block_reduce2(float& s, float& s2) {
    __shared__ float sh[2][32];
    int tid = threadIdx.x;
#pragma unroll
    for (int o = 16; o; o >>= 1) {
        s  += __shfl_xor_sync(0xffffffffu, s, o);
        s2 += __shfl_xor_sync(0xffffffffu, s2, o);
    }
    __syncthreads();
    if ((tid & 31) == 0) { sh[0][tid >> 5] = s; sh[1][tid >> 5] = s2; }
    __syncthreads();
    int nw = blockDim.x >> 5;
    float a = 0.f, b = 0.f;
    for (int i = 0; i < nw; i++) { a += sh[0][i]; b += sh[1][i]; }
    s = a; s2 = b;
}

// ---------------- K0: zero the ADMM state buffers ----------------
__global__ void k_zero(float* a, float* b, int n) {
    int i = blockIdx.x * blockDim.x + threadIdx.x;
    if (i < n) { a[i] = 0.f; b[i] = 0.f; }
}

// ---------------- K1: patchify + LN(768) + pos_emb ----------------
__global__ void k_patch_ln(const float* __restrict__ img,
                           const float* __restrict__ lg,
                           const float* __restrict__ lb,
                           const float* __restrict__ pos) {
    int blk = blockIdx.x;
    int b = blk / NTOK, n = blk % NTOK;
    int hh = n / 14, ww = n % 14;
    int tid = threadIdx.x;
    float v[3];
    float s = 0.f, s2 = 0.f;
#pragma unroll
    for (int t = 0; t < 3; t++) {
        int d = tid + t * 256;
        int c = d >> 8, r = d & 255, ph = r >> 4, pw = r & 15;
        float x = img[((b * CCH + c) * HH + hh * 16 + ph) * HH + ww * 16 + pw];
        v[t] = x; s += x; s2 += x * x;
    }
    block_reduce2(s, s2);
    float mu = s * (1.f / 768.f);
    float var = s2 * (1.f / 768.f) - mu * mu;
    float rs = rsqrtf(var + LNEPS);
#pragma unroll
    for (int t = 0; t < 3; t++) {
        int d = tid + t * 256;
        g_x[(b * NTOK + n) * PD + d] = (v[t] - mu) * rs * lg[d] + lb[d] + pos[n * PD + d];
    }
}

// ---------------- K2: projection GEMM (NN): [6272,768]x[768,512]+bias ----------------
// writes into padded [B,224,512] layout
__global__ void k_proj(const float* __restrict__ X, const float* __restrict__ W,
                       const float* __restrict__ bias, float* __restrict__ out) {
    __shared__ float As[16][68], Bs[16][68];
    int m0 = blockIdx.x * 64, n0 = blockIdx.y * 64;
    int tid = threadIdx.x;
    int tx = tid & 15, ty = tid >> 4;
    int arow = tid >> 2, acg = (tid & 3) * 4;
    int brow = tid >> 4, bcol = (tid & 15) * 4;
    float acc[4][4] = {};
    for (int k0 = 0; k0 < PD; k0 += 16) {
        float4 a = *(const float4*)&X[(m0 + arow) * PD + k0 + acg];
        As[acg + 0][arow] = a.x; As[acg + 1][arow] = a.y;
        As[acg + 2][arow] = a.z; As[acg + 3][arow] = a.w;
        *(float4*)&Bs[brow][bcol] = *(const float4*)&W[(k0 + brow) * DIM + n0 + bcol];
        __syncthreads();
#pragma unroll
        for (int kk = 0; kk < 16; kk++) {
            float4 a4 = *(float4*)&As[kk][ty * 4];
            float4 b4 = *(float4*)&Bs[kk][tx * 4];
            acc[0][0] += a4.x * b4.x; acc[0][1] += a4.x * b4.y; acc[0][2] += a4.x * b4.z; acc[0][3] += a4.x * b4.w;
            acc[1][0] += a4.y * b4.x; acc[1][1] += a4.y * b4.y; acc[1][2] += a4.y * b4.z; acc[1][3] += a4.y * b4.w;
            acc[2][0] += a4.z * b4.x; acc[2][1] += a4.z * b4.y; acc[2][2] += a4.z * b4.z; acc[2][3] += a4.z * b4.w;
            acc[3][0] += a4.w * b4.x; acc[3][1] += a4.w * b4.y; acc[3][2] += a4.w * b4.z; acc[3][3] += a4.w * b4.w;
        }
        __syncthreads();
    }
#pragma unroll
    for (int i = 0; i < 4; i++) {
        int gm = m0 + ty * 4 + i;
        int b = gm / NTOK, nn = gm % NTOK;
#pragma unroll
        for (int j = 0; j < 4; j++) {
            int gc = n0 + tx * 4 + j;
            out[(b * NP + nn) * DIM + gc] = acc[i][j] + bias[gc];
        }
    }
}

// ---------------- K3: LN over 512 (in place), optional scale (V /= 196) ----------------
__global__ void k_ln512(float* __restrict__ buf, const float* __restrict__ lg,
                        const float* __restrict__ lb, float scale) {
    int blk = blockIdx.x;
    int b = blk / NTOK, n = blk % NTOK;
    float* row = buf + (b * NP + n) * DIM;
    int tid = threadIdx.x;   // 128
    float4 v = ((float4*)row)[tid];
    float s = v.x + v.y + v.z + v.w;
    float s2 = v.x * v.x + v.y * v.y + v.z * v.z + v.w * v.w;
    block_reduce2(s, s2);
    float mu = s * (1.f / 512.f);
    float rs = rsqrtf(s2 * (1.f / 512.f) - mu * mu + LNEPS);
    float4 g4 = ((const float4*)lg)[tid], b4 = ((const float4*)lb)[tid];
    v.x = ((v.x - mu) * rs * g4.x + b4.x) * scale;
    v.y = ((v.y - mu) * rs * g4.y + b4.y) * scale;
    v.z = ((v.z - mu) * rs * g4.z + b4.z) * scale;
    v.w = ((v.w - mu) * rs * g4.w + b4.w) * scale;
    ((float4*)row)[tid] = v;
}

// ---------------- K4/K5: per-batch NT Gram GEMM, K=512 ----------------
// mode 0: A = 2*A.Bt + I (A,B = V,V)    mode 1: P = -2*Q.Vt + 1/196 (guarded, pads=0)
__global__ void k_gram(const float* __restrict__ Abase, const float* __restrict__ Bbase,
                       float* __restrict__ out, int mode) {
    int b = blockIdx.z;
    const float* Ab = Abase + b * NP * DIM;
    const float* Bb = Bbase + b * NP * DIM;
    __shared__ float As[16][68], Bs[16][68];
    int m0 = blockIdx.x * 64, n0 = blockIdx.y * 64;
    int tid = threadIdx.x;
    int tx = tid & 15, ty = tid >> 4;
    int arow = tid >> 2, acg = (tid & 3) * 4;
    float acc[4][4] = {};
    for (int k0 = 0; k0 < DIM; k0 += 16) {
        float4 a = *(const float4*)&Ab[(m0 + arow) * DIM + k0 + acg];
        As[acg + 0][arow] = a.x; As[acg + 1][arow] = a.y;
        As[acg + 2][arow] = a.z; As[acg + 3][arow] = a.w;
        float4 bb = *(const float4*)&Bb[(n0 + arow) * DIM + k0 + acg];
        Bs[acg + 0][arow] = bb.x; Bs[acg + 1][arow] = bb.y;
        Bs[acg + 2][arow] = bb.z; Bs[acg + 3][arow] = bb.w;
        __syncthreads();
#pragma unroll
        for (int kk = 0; kk < 16; kk++) {
            float4 a4 = *(float4*)&As[kk][ty * 4];
            float4 b4 = *(float4*)&Bs[kk][tx * 4];
            acc[0][0] += a4.x * b4.x; acc[0][1] += a4.x * b4.y; acc[0][2] += a4.x * b4.z; acc[0][3] += a4.x * b4.w;
            acc[1][0] += a4.y * b4.x; acc[1][1] += a4.y * b4.y; acc[1][2] += a4.y * b4.z; acc[1][3] += a4.y * b4.w;
            acc[2][0] += a4.z * b4.x; acc[2][1] += a4.z * b4.y; acc[2][2] += a4.z * b4.z; acc[2][3] += a4.z * b4.w;
            acc[3][0] += a4.w * b4.x; acc[3][1] += a4.w * b4.y; acc[3][2] += a4.w * b4.z; acc[3][3] += a4.w * b4.w;
        }
        __syncthreads();
    }
#pragma unroll
    for (int i = 0; i < 4; i++) {
        int gm = m0 + ty * 4 + i;
        if (gm >= NP) continue;
#pragma unroll
        for (int j = 0; j < 4; j++) {
            int gn = n0 + tx * 4 + j;
            if (gn >= NP) continue;
            float val;
            if (mode == 0) {
                val = 2.f * acc[i][j] + ((gm == gn) ? 1.f : 0.f);   // rho = 1
            } else {
                val = (gm < NTOK && gn < NTOK) ? (-2.f * acc[i][j] + (1.f / 196.f)) : 0.f;
            }
            out[b * NPS + gm * NP + gn] = val;
        }
    }
}

// ---------------- K6: per-batch Gauss-Jordan inverse (196x196, SPD >= I: no pivoting) ----------------
extern __shared__ float sA[];   // 196*197 floats
__global__ void k_inv(const float* __restrict__ Ain, float* __restrict__ Mout) {
    int b = blockIdx.x;
    int tid = threadIdx.x;      // 512
    const float* A = Ain + b * NPS;
    float* Mi = Mout + b * NPS;
    for (int i = tid; i < 196 * 196; i += 512) {
        int r = i / 196, c = i % 196;
        sA[r * 197 + c] = A[r * NP + c];
    }
    __shared__ float s_pivinv;
    int wid = tid >> 5, lane = tid & 31;
    for (int k = 0; k < 196; k++) {
        __syncthreads();
        if (tid == 0) s_pivinv = 1.0f / sA[k * 197 + k];
        __syncthreads();
        float pv = s_pivinv;
        if (tid < 196)
            sA[k * 197 + tid] = ((tid == k) ? 1.0f : sA[k * 197 + tid]) * pv;
        __syncthreads();
        float rk[7];
#pragma unroll
        for (int t = 0; t < 7; t++) {
            int j = lane + 32 * t;
            rk[t] = (j < 196) ? sA[k * 197 + j] : 0.f;
        }
        for (int i = wid; i < 196; i += 16) {
            if (i == k) continue;
            float f = sA[i * 197 + k];
#pragma unroll
            for (int t = 0; t < 7; t++) {
                int j = lane + 32 * t;
                if (j < 196) {
                    float val = ((j == k) ? 0.f : sA[i * 197 + j]) - f * rk[t];
                    sA[i * 197 + j] = val;
                }
            }
        }
    }
    __syncthreads();
    for (int i = tid; i < NPS; i += 512) {
        int r = i / NP, c = i % NP;
        Mi[i] = (r < 196 && c < 196) ? sA[r * 197 + c] : 0.f;
    }
}

// ---------------- K7: fused ADMM iteration (RHS build + GEMM + clip update) ----------------
// X = RHS @ Minv  (Minv symmetric), RHS = (Z - U) - P ; Z' = clip(X+U,0,1); U' = U + X - Z'
__global__ void k_admm(const float* __restrict__ Zin, const float* __restrict__ Uin,
                       float* __restrict__ Zout, float* __restrict__ Uout,
                       const float* __restrict__ Pg, const float* __restrict__ Mg) {
    int b = blockIdx.z;
    const float* Zb = Zin + b * NPS;
    const float* Ub = Uin + b * NPS;
    const float* Pb = Pg + b * NPS;
    const float* Mb = Mg + b * NPS;
    __shared__ float As[16][68], Bs[16][68];
    int m0 = blockIdx.x * 64;   // token rows n
    int n0 = blockIdx.y * 64;   // output cols i
    int tid = threadIdx.x;
    int tx = tid & 15, ty = tid >> 4;
    int arow = tid >> 2, acg = (tid & 3) * 4;
    int brow = tid >> 4, bcol = (tid & 15) * 4;
    float acc[4][4] = {};
    for (int k0 = 0; k0 < NP; k0 += 16) {
        int aidx = (m0 + arow) * NP + k0 + acg;
        float4 z4 = *(const float4*)&Zb[aidx];
        float4 u4 = *(const float4*)&Ub[aidx];
        float4 p4 = *(const float4*)&Pb[aidx];
        As[acg + 0][arow] = (z4.x - u4.x) - p4.x;
        As[acg + 1][arow] = (z4.y - u4.y) - p4.y;
        As[acg + 2][arow] = (z4.z - u4.z) - p4.z;
        As[acg + 3][arow] = (z4.w - u4.w) - p4.w;
        *(float4*)&Bs[brow][bcol] = *(const float4*)&Mb[(k0 + brow) * NP + n0 + bcol];
        __syncthreads();
#pragma unroll
        for (int kk = 0; kk < 16; kk++) {
            float4 a4 = *(float4*)&As[kk][ty * 4];
            float4 b4 = *(float4*)&Bs[kk][tx * 4];
            acc[0][0] += a4.x * b4.x; acc[0][1] += a4.x * b4.y; acc[0][2] += a4.x * b4.z; acc[0][3] += a4.x * b4.w;
            acc[1][0] += a4.y * b4.x; acc[1][1] += a4.y * b4.y; acc[1][2] += a4.y * b4.z; acc[1][3] += a4.y * b4.w;
            acc[2][0] += a4.z * b4.x; acc[2][1] += a4.z * b4.y; acc[2][2] += a4.z * b4.z; acc[2][3] += a4.z * b4.w;
            acc[3][0] += a4.w * b4.x; acc[3][1] += a4.w * b4.y; acc[3][2] += a4.w * b4.z; acc[3][3] += a4.w * b4.w;
        }
        __syncthreads();
    }
#pragma unroll
    for (int i = 0; i < 4; i++) {
        int gn = m0 + ty * 4 + i;
        if (gn >= NP) continue;
#pragma unroll
        for (int j = 0; j < 4; j++) {
            int gi = n0 + tx * 4 + j;
            if (gi >= NP) continue;
            int o = gn * NP + gi;
            float u = Ub[o];
            float x = acc[i][j];
            float zz = x + u;
            zz = fminf(fmaxf(zz, 0.f), 1.f);
            Zout[b * NPS + o] = zz;
            Uout[b * NPS + o] = u + x - zz;
        }
    }
}

// ---------------- K8: pooled[b,d] = (1/196) sum_n sum_m (z/rowsum) V ----------------
__global__ void k_pool(const float* __restrict__ Zfin) {
    int b = blockIdx.x;
    int tid = threadIdx.x;   // 256
    __shared__ float sS[196], sW[196];
    const float* Zb = Zfin + b * NPS;
    if (tid < 196) {
        float s = 0.f;
        const float* row = Zb + tid * NP;
        for (int m = 0; m < 196; m++) s += fabsf(row[m]);
        sS[tid] = s + 1e-10f;
    }
    __syncthreads();
    if (tid < 196) {
        float w = 0.f;
        for (int n = 0; n < 196; n++) w += Zb[n * NP + tid] / sS[n];
        sW[tid] = w * (1.f / 196.f);
    }
    __syncthreads();
    const float* Vb = g_V + b * NP * DIM;
    for (int d = tid; d < DIM; d += 256) {
        float acc = 0.f;
        for (int m = 0; m < 196; m++) acc += sW[m] * Vb[m * DIM + d];
        g_pooled[b * DIM + d] = acc;
    }
}

// ---------------- K9: LN(pooled) @ mlp_w + bias, softmax ----------------
__global__ void k_head(const float* __restrict__ lg, const float* __restrict__ lb,
                       const float* __restrict__ W, const float* __restrict__ bias,
                       float* __restrict__ out) {
    int b = blockIdx.x;
    int tid = threadIdx.x;   // 256
    __shared__ float sx[DIM];
    float s = 0.f, s2 = 0.f;
    for (int d = tid; d < DIM; d += 256) {
        float v = g_pooled[b * DIM + d];
        sx[d] = v; s += v; s2 += v * v;
    }
    block_reduce2(s, s2);
    float mu = s * (1.f / 512.f);
    float rs = rsqrtf(s2 * (1.f / 512.f) - mu * mu + LNEPS);
    __syncthreads();
    for (int d = tid; d < DIM; d += 256) sx[d] = (sx[d] - mu) * rs * lg[d] + lb[d];
    __syncthreads();
    float lgts[4];
    float mx = -1e30f;
#pragma unroll
    for (int t = 0; t < 4; t++) {
        int c = tid + t * 256;
        if (c < NCLS) {
            float acc = bias[c];
            for (int d = 0; d < DIM; d++) acc += sx[d] * W[d * NCLS + c];
            lgts[t] = acc;
            mx = fmaxf(mx, acc);
        } else lgts[t] = -1e30f;
    }
    __shared__ float red[32];
    for (int o = 16; o; o >>= 1) mx = fmaxf(mx, __shfl_xor_sync(0xffffffffu, mx, o));
    if ((tid & 31) == 0) red[tid >> 5] = mx;
    __syncthreads();
    float bm = red[0];
    for (int i = 1; i < 8; i++) bm = fmaxf(bm, red[i]);
    float es = 0.f;
#pragma unroll
    for (int t = 0; t < 4; t++) {
        int c = tid + t * 256;
        if (c < NCLS) { lgts[t] = expf(lgts[t] - bm); es += lgts[t]; }
    }
    float dummy = 0.f;
    block_reduce2(es, dummy);
#pragma unroll
    for (int t = 0; t < 4; t++) {
        int c = tid + t * 256;
        if (c < NCLS) out[b * NCLS + c] = lgts[t] / es;
    }
}

// ---------------- host ----------------
extern "C" void kernel_launch(void* const* d_in, const int* in_sizes, int n_in,
                              void* d_out, int out_size) {
    const float* img    = (const float*)d_in[0];
    const float* ln_pg  = (const float*)d_in[1];
    const float* ln_pb  = (const float*)d_in[2];
    const float* wq_w   = (const float*)d_in[3];
    const float* wq_b   = (const float*)d_in[4];
    const float* lnq_g  = (const float*)d_in[5];
    const float* lnq_b  = (const float*)d_in[6];
    const float* wv_w   = (const float*)d_in[7];
    const float* wv_b   = (const float*)d_in[8];
    const float* lnv_g  = (const float*)d_in[9];
    const float* lnv_b  = (const float*)d_in[10];
    const float* pos    = (const float*)d_in[11];
    const float* mlp_g  = (const float*)d_in[12];
    const float* mlp_b  = (const float*)d_in[13];
    const float* mlp_w  = (const float*)d_in[14];
    const float* mlp_bs = (const float*)d_in[15];
    float* out = (float*)d_out;

    float *px, *pq, *pv, *pa, *pm, *pp, *pz, *pu;
    cudaGetSymbolAddress((void**)&px, g_x);
    cudaGetSymbolAddress((void**)&pq, g_Q);
    cudaGetSymbolAddress((void**)&pv, g_V);
    cudaGetSymbolAddress((void**)&pa, g_A);
    cudaGetSymbolAddress((void**)&pm, g_Minv);
    cudaGetSymbolAddress((void**)&pp, g_P);
    cudaGetSymbolAddress((void**)&pz, g_Zbuf);
    cudaGetSymbolAddress((void**)&pu, g_Ubuf);
    const int ZSTR = BATCH * NPS + SLK_M;
    float* pz0 = pz;        float* pz1 = pz + ZSTR;
    float* pu0 = pu;        float* pu1 = pu + ZSTR;

    cudaFuncSetAttribute(k_inv, cudaFuncAttributeMaxDynamicSharedMemorySize, 196 * 197 * 4);

    // zero ADMM state (must be re-zeroed every launch for determinism)
    {
        int n = ZSTR;
        k_zero<<<(n + 255) / 256, 256>>>(pz0, pu0, n);
    }
    // 1) patchify + LN + pos
    k_patch_ln<<<BATCH * NTOK, 256>>>(img, ln_pg, ln_pb, pos);
    // 2) projections
    dim3 gp(98, 8);
    k_proj<<<gp, 256>>>(px, wq_w, wq_b, pq);
    k_proj<<<gp, 256>>>(px, wv_w, wv_b, pv);
    // 3) LayerNorms (V also scaled by 1/196)
    k_ln512<<<BATCH * NTOK, 128>>>(pq, lnq_g, lnq_b, 1.0f);
    k_ln512<<<BATCH * NTOK, 128>>>(pv, lnv_g, lnv_b, 1.0f / 196.0f);
    // 4) Gram matrices
    dim3 gg(4, 4, BATCH);
    k_gram<<<gg, 256>>>(pv, pv, pa, 0);   // A = 2 V V^T + I
    k_gram<<<gg, 256>>>(pq, pv, pp, 1);   // P = -2 Q V^T + 1/196 (guarded)
    // 5) inverse
    k_inv<<<BATCH, 512, 196 * 197 * 4>>>(pa, pm);
    // 6) ADMM iterations (double-buffered)
    for (int t = 0; t < ITERS; t++) {
        const float* zi = (t & 1) ? pz1 : pz0;
        const float* ui = (t & 1) ? pu1 : pu0;
        float* zo = (t & 1) ? pz0 : pz1;
        float* uo = (t & 1) ? pu0 : pu1;
        k_admm<<<gg, 256>>>(zi, ui, zo, uo, pp, pm);
    }
    // after 50 iters (t=49 odd) final Z is in buffer 0
    // 7) pooled
    k_pool<<<BATCH, 256>>>(pz0);
    // 8) head
    k_head<<<BATCH, 256>>>(mlp_g, mlp_b, mlp_w, mlp_bs, out);
}